// round 12
// baseline (speedup 1.0000x reference)
#include <cuda_runtime.h>
#include <cstdint>
#include <cstddef>

#define N_ITEMS   100000
#define N_USERS   16384
#define HIST      50
#define TEXT_DIM  256
#define GCN_DIM   128
#define HIDDEN_DIM 512
#define TOWER_DIM 128
#define FEAT_DIM  (TEXT_DIM + GCN_DIM)   // 384

#define CDIV(a,b) (((a)+(b)-1)/(b))

// ---------------- scratch (device globals; no allocation allowed) ----------
__device__ float g_H[(size_t)N_ITEMS * HIDDEN_DIM];        // item hidden (tf32 bits)
__device__ float g_item_emb[(size_t)N_ITEMS * TOWER_DIM];  // item tower out (fp32)
__device__ float g_user_feat[(size_t)N_USERS * (GCN_DIM + TOWER_DIM)]; // tf32 bits
__device__ float g_Hu[(size_t)N_USERS * HIDDEN_DIM];       // user hidden (tf32 bits)
// truncated weights, packed: W1i | W2i | W1u | W2u
#define W1I_OFF 0
#define W2I_OFF (FEAT_DIM * HIDDEN_DIM)                        // 196608
#define W1U_OFF (W2I_OFF + HIDDEN_DIM * TOWER_DIM)             // 262144
#define W2U_OFF (W1U_OFF + (GCN_DIM + TOWER_DIM) * HIDDEN_DIM) // 393216
#define W_TOTAL (W2U_OFF + HIDDEN_DIM * TOWER_DIM)             // 458752
__device__ float g_Wc[W_TOTAL];

__device__ __forceinline__ float f2tf32f(float x) {
    unsigned r;
    asm("cvt.rna.tf32.f32 %0, %1;" : "=r"(r) : "f"(x));
    return __uint_as_float(r);
}
__device__ __forceinline__ unsigned f2tf32u(float x) {
    unsigned r;
    asm("cvt.rna.tf32.f32 %0, %1;" : "=r"(r) : "f"(x));
    return r;
}

__device__ __forceinline__ void mma_tf32(float* d, const unsigned* a, const unsigned* b) {
    asm volatile(
        "mma.sync.aligned.m16n8k8.row.col.f32.tf32.tf32.f32 "
        "{%0,%1,%2,%3}, {%4,%5,%6,%7}, {%8,%9}, {%0,%1,%2,%3};\n"
        : "+f"(d[0]), "+f"(d[1]), "+f"(d[2]), "+f"(d[3])
        : "r"(a[0]), "r"(a[1]), "r"(a[2]), "r"(a[3]), "r"(b[0]), "r"(b[1]));
}

__device__ __forceinline__ void cp16(uint32_t dst, const void* src, int szbytes) {
    asm volatile("cp.async.ca.shared.global [%0], [%1], 16, %2;"
                 :: "r"(dst), "l"(src), "r"(szbytes));
}

// --------- one-shot fused weight conversion -> tf32 (packed into g_Wc) -----
__global__ __launch_bounds__(256)
void convert_weights(const float* __restrict__ w1i, const float* __restrict__ w2i,
                     const float* __restrict__ w1u, const float* __restrict__ w2u,
                     float* __restrict__ dst)
{
    const int i = blockIdx.x * blockDim.x + threadIdx.x;
    if (i >= W_TOTAL) return;
    float v;
    if      (i < W2I_OFF) v = w1i[i - W1I_OFF];
    else if (i < W1U_OFF) v = w2i[i - W2I_OFF];
    else if (i < W2U_OFF) v = w1u[i - W1U_OFF];
    else                  v = w2u[i - W2U_OFF];
    dst[i] = f2tf32f(v);
}

// ---------------- TF32 tensor-core GEMM, cp.async double-buffered ----------
// A logical [M,K]; col c < split from A0 (lda=split) else A1 (lda=K-split).
// B [K,N] row-major, tf32-truncated.  BM=BN=128, BK=16, 256 threads (8 warps,
// 64x32 warp tile, 4x4 m16n8k8).  ACVT: apply cvt.rna.tf32 to A fragments
// (needed only when A is raw input).  WTRUNC: store C pre-truncated.
// L2NORM requires N==128 (gridDim.x==1).
template<bool RELU, bool L2NORM, bool WTRUNC, bool ACVT>
__global__ __launch_bounds__(256, 2)
void mma_gemm(const float* __restrict__ A0, const float* __restrict__ A1, int split,
              int M, int N, int K,
              const float* __restrict__ B, const float* __restrict__ bias,
              float* __restrict__ C)
{
    constexpr int BM = 128, BN = 128, BK = 16;
    constexpr int LDA = BK + 4;      // 20: (20g+t4)%32 covers all 32 banks
    constexpr int LDB = BN + 8;      // 136: conflict-free fragment loads
    constexpr int A_BUF = BM * LDA;
    constexpr int B_BUF = BK * LDB;
    __shared__ __align__(16) float smem[2 * A_BUF + 2 * B_BUF];

    float* As = smem;
    float* Bs = smem + 2 * A_BUF;
    float (*red)[17] = reinterpret_cast<float(*)[17]>(smem);  // epilogue alias
    float* scl = smem + BM * 17;

    const int tid  = threadIdx.x;
    const int warp = tid >> 5, lane = tid & 31;
    const int wy = warp >> 2, wx = warp & 3;
    const int g  = lane >> 2, t4 = lane & 3;
    const int bm = blockIdx.y, bn = blockIdx.x;
    const int lda1 = K - split;

    const uint32_t a_base = (uint32_t)__cvta_generic_to_shared(As);
    const uint32_t b_base = (uint32_t)__cvta_generic_to_shared(Bs);

    float acc[4][4][4];
    #pragma unroll
    for (int i = 0; i < 4; i++)
        #pragma unroll
        for (int j = 0; j < 4; j++)
            #pragma unroll
            for (int r = 0; r < 4; r++) acc[i][j][r] = 0.f;

    auto issue = [&](int k0, int buf) {
        #pragma unroll
        for (int c = 0; c < 2; c++) {
            const int id = tid + c * 256;        // 0..511
            const int m  = id >> 2;
            const int f  = (id & 3) * 4;
            const int grow = bm * BM + m;
            const int ac = k0 + f;
            const float* src = A0;
            int sz = 0;
            if (grow < M) {
                src = (ac < split) ? (A0 + (size_t)grow * split + ac)
                                   : (A1 + (size_t)grow * lda1 + (ac - split));
                sz = 16;
            }
            cp16(a_base + (uint32_t)(buf * A_BUF + m * LDA + f) * 4, src, sz);
        }
        #pragma unroll
        for (int c = 0; c < 2; c++) {
            const int id = tid + c * 256;
            const int kb = id >> 5;
            const int nb = (id & 31) * 4;
            const float* src = B + (size_t)(k0 + kb) * N + (size_t)bn * BN + nb;
            cp16(b_base + (uint32_t)(buf * B_BUF + kb * LDB + nb) * 4, src, 16);
        }
        asm volatile("cp.async.commit_group;");
    };

    const int NT = K / BK;
    issue(0, 0);

    for (int it = 0; it < NT; it++) {
        const int buf = it & 1;
        if (it + 1 < NT) {
            issue((it + 1) * BK, buf ^ 1);
            asm volatile("cp.async.wait_group 1;");
        } else {
            asm volatile("cp.async.wait_group 0;");
        }
        __syncthreads();

        const float*    Abf = As + buf * A_BUF;
        const unsigned* Abu = reinterpret_cast<const unsigned*>(Abf);
        const unsigned* Bbu = reinterpret_cast<const unsigned*>(Bs + buf * B_BUF);

        #pragma unroll
        for (int ks = 0; ks < 2; ks++) {
            const int kb = ks * 8;
            unsigned a[4][4], b[4][2];
            #pragma unroll
            for (int mi = 0; mi < 4; mi++) {
                const int rb = wy * 64 + mi * 16;
                if (ACVT) {
                    a[mi][0] = f2tf32u(Abf[(rb + g)     * LDA + kb + t4]);
                    a[mi][1] = f2tf32u(Abf[(rb + 8 + g) * LDA + kb + t4]);
                    a[mi][2] = f2tf32u(Abf[(rb + g)     * LDA + kb + 4 + t4]);
                    a[mi][3] = f2tf32u(Abf[(rb + 8 + g) * LDA + kb + 4 + t4]);
                } else {
                    a[mi][0] = Abu[(rb + g)     * LDA + kb + t4];
                    a[mi][1] = Abu[(rb + 8 + g) * LDA + kb + t4];
                    a[mi][2] = Abu[(rb + g)     * LDA + kb + 4 + t4];
                    a[mi][3] = Abu[(rb + 8 + g) * LDA + kb + 4 + t4];
                }
            }
            #pragma unroll
            for (int ni = 0; ni < 4; ni++) {
                const int nbc = wx * 32 + ni * 8;
                b[ni][0] = Bbu[(kb + t4)     * LDB + nbc + g];
                b[ni][1] = Bbu[(kb + 4 + t4) * LDB + nbc + g];
            }
            #pragma unroll
            for (int mi = 0; mi < 4; mi++)
                #pragma unroll
                for (int ni = 0; ni < 4; ni++)
                    mma_tf32(acc[mi][ni], a[mi], b[ni]);
        }
        __syncthreads();
    }

    // ---- epilogue: bias (+ReLU) ----
    #pragma unroll
    for (int ni = 0; ni < 4; ni++) {
        const int colw = wx * 32 + ni * 8 + t4 * 2;
        const float b0 = bias[bn * BN + colw];
        const float b1 = bias[bn * BN + colw + 1];
        #pragma unroll
        for (int mi = 0; mi < 4; mi++) {
            float v0 = acc[mi][ni][0] + b0;
            float v1 = acc[mi][ni][1] + b1;
            float v2 = acc[mi][ni][2] + b0;
            float v3 = acc[mi][ni][3] + b1;
            if (RELU) {
                v0 = fmaxf(v0, 0.f); v1 = fmaxf(v1, 0.f);
                v2 = fmaxf(v2, 0.f); v3 = fmaxf(v3, 0.f);
            }
            acc[mi][ni][0] = v0; acc[mi][ni][1] = v1;
            acc[mi][ni][2] = v2; acc[mi][ni][3] = v3;
        }
    }

    if (L2NORM) {
        const int slot = wx * 4 + t4;
        #pragma unroll
        for (int mi = 0; mi < 4; mi++) {
            const int rb = wy * 64 + mi * 16;
            float s0 = 0.f, s1 = 0.f;
            #pragma unroll
            for (int ni = 0; ni < 4; ni++) {
                s0 = fmaf(acc[mi][ni][0], acc[mi][ni][0], s0);
                s0 = fmaf(acc[mi][ni][1], acc[mi][ni][1], s0);
                s1 = fmaf(acc[mi][ni][2], acc[mi][ni][2], s1);
                s1 = fmaf(acc[mi][ni][3], acc[mi][ni][3], s1);
            }
            red[rb + g][slot]     = s0;
            red[rb + 8 + g][slot] = s1;
        }
        __syncthreads();
        if (tid < BM) {
            float s = 0.f;
            #pragma unroll
            for (int t = 0; t < 16; t++) s += red[tid][t];
            scl[tid] = 1.f / fmaxf(sqrtf(s), 1e-12f);
        }
        __syncthreads();
        #pragma unroll
        for (int mi = 0; mi < 4; mi++) {
            const int rb = wy * 64 + mi * 16;
            const float s0 = scl[rb + g];
            const float s1 = scl[rb + 8 + g];
            #pragma unroll
            for (int ni = 0; ni < 4; ni++) {
                acc[mi][ni][0] *= s0; acc[mi][ni][1] *= s0;
                acc[mi][ni][2] *= s1; acc[mi][ni][3] *= s1;
            }
        }
    }

    // ---- store ----
    #pragma unroll
    for (int mi = 0; mi < 4; mi++) {
        const int row0 = bm * BM + wy * 64 + mi * 16 + g;
        const int row1 = row0 + 8;
        #pragma unroll
        for (int ni = 0; ni < 4; ni++) {
            const int col = bn * BN + wx * 32 + ni * 8 + t4 * 2;
            float o0 = acc[mi][ni][0], o1 = acc[mi][ni][1];
            float o2 = acc[mi][ni][2], o3 = acc[mi][ni][3];
            if (WTRUNC) {
                o0 = f2tf32f(o0); o1 = f2tf32f(o1);
                o2 = f2tf32f(o2); o3 = f2tf32f(o3);
            }
            if (row0 < M)
                *reinterpret_cast<float2*>(C + (size_t)row0 * N + col) = make_float2(o0, o1);
            if (row1 < M)
                *reinterpret_cast<float2*>(C + (size_t)row1 * N + col) = make_float2(o2, o3);
        }
    }
}

// ---------------- history gather + mean pool + fuse (tf32-truncated out) ---
__global__ __launch_bounds__(128)
void gather_kernel(const float* __restrict__ gcn_user,
                   const int* __restrict__ hist,
                   const float* __restrict__ item_emb,
                   float* __restrict__ user_feat)
{
    const int u = blockIdx.x;
    const int t = threadIdx.x;  // 0..127 = embedding dim
    __shared__ int sidx[HIST];
    if (t < HIST) sidx[t] = hist[u * HIST + t];
    __syncthreads();

    float s = 0.f;
    #pragma unroll
    for (int j = 0; j < HIST; j++)
        s += item_emb[(size_t)sidx[j] * TOWER_DIM + t];

    user_feat[(size_t)u * (GCN_DIM + TOWER_DIM) + t] =
        f2tf32f(gcn_user[(size_t)u * GCN_DIM + t]);
    user_feat[(size_t)u * (GCN_DIM + TOWER_DIM) + GCN_DIM + t] =
        f2tf32f(s * (1.0f / HIST));
}

// ---------------- launch -----------------------------------------------------
extern "C" void kernel_launch(void* const* d_in, const int* in_sizes, int n_in,
                              void* d_out, int out_size)
{
    const float* item_text = (const float*)d_in[0];
    const float* gcn_item  = (const float*)d_in[1];
    const float* gcn_user  = (const float*)d_in[2];
    const int*   hist      = (const int*)  d_in[3];
    const float* W1i = (const float*)d_in[4];
    const float* b1i = (const float*)d_in[5];
    const float* W2i = (const float*)d_in[6];
    const float* b2i = (const float*)d_in[7];
    const float* W1u = (const float*)d_in[8];
    const float* b1u = (const float*)d_in[9];
    const float* W2u = (const float*)d_in[10];
    const float* b2u = (const float*)d_in[11];
    float* out = (float*)d_out;

    float *pH, *pItem, *pUF, *pHu, *pW;
    cudaGetSymbolAddress((void**)&pH,    g_H);
    cudaGetSymbolAddress((void**)&pItem, g_item_emb);
    cudaGetSymbolAddress((void**)&pUF,   g_user_feat);
    cudaGetSymbolAddress((void**)&pHu,   g_Hu);
    cudaGetSymbolAddress((void**)&pW,    g_Wc);

    // one-shot fused weight conversion (1.8 MB, ~3us)
    convert_weights<<<CDIV(W_TOTAL, 256), 256>>>(W1i, W2i, W1u, W2u, pW);

    const dim3 blk(256);

    // Item tower L1: H = relu(concat(text,gcn) @ W1i + b1i); A raw -> ACVT;
    // output stored tf32-truncated.
    mma_gemm<true, false, true, true><<<dim3(HIDDEN_DIM / 128, CDIV(N_ITEMS, 128)), blk>>>(
        item_text, gcn_item, TEXT_DIM,
        N_ITEMS, HIDDEN_DIM, FEAT_DIM, pW + W1I_OFF, b1i, pH);

    // Item tower L2: item_emb = l2norm(H @ W2i + b2i); A pre-trunc; out fp32
    mma_gemm<false, true, false, false><<<dim3(1, CDIV(N_ITEMS, 128)), blk>>>(
        pH, nullptr, HIDDEN_DIM,
        N_ITEMS, TOWER_DIM, HIDDEN_DIM, pW + W2I_OFF, b2i, pItem);

    // History gather + mean pool fused with gcn_user (tf32-truncated out)
    gather_kernel<<<N_USERS, 128>>>(gcn_user, hist, pItem, pUF);

    // User tower L1: Hu = relu(user_feat @ W1u + b1u); A pre-trunc; out trunc
    mma_gemm<true, false, true, false><<<dim3(HIDDEN_DIM / 128, CDIV(N_USERS, 128)), blk>>>(
        pUF, nullptr, GCN_DIM + TOWER_DIM,
        N_USERS, HIDDEN_DIM, GCN_DIM + TOWER_DIM, pW + W1U_OFF, b1u, pHu);

    // User tower L2: out = l2norm(Hu @ W2u + b2u); A pre-trunc; out fp32
    mma_gemm<false, true, false, false><<<dim3(1, CDIV(N_USERS, 128)), blk>>>(
        pHu, nullptr, HIDDEN_DIM,
        N_USERS, TOWER_DIM, HIDDEN_DIM, pW + W2U_OFF, b2u, out);
}

// round 17
// speedup vs baseline: 2.1981x; 2.1981x over previous
#include <cuda_runtime.h>
#include <cuda_fp16.h>
#include <cstdint>
#include <cstddef>

#define N_ITEMS   100000
#define N_USERS   16384
#define HIST      50
#define TEXT_DIM  256
#define GCN_DIM   128
#define HIDDEN_DIM 512
#define TOWER_DIM 128
#define FEAT_DIM  (TEXT_DIM + GCN_DIM)   // 384

#define CDIV(a,b) (((a)+(b)-1)/(b))

// ---------------- scratch (device globals; no allocation allowed) ----------
__device__ __half g_Af16[(size_t)N_ITEMS * FEAT_DIM];       // fused fp16 item feats
__device__ __half g_H[(size_t)N_ITEMS * HIDDEN_DIM];        // item hidden (fp16)
__device__ float  g_item_emb[(size_t)N_ITEMS * TOWER_DIM];  // item tower out (fp32)
__device__ __half g_user_feat[(size_t)N_USERS * (GCN_DIM + TOWER_DIM)]; // fp16
__device__ __half g_Hu[(size_t)N_USERS * HIDDEN_DIM];       // user hidden (fp16)
// fp16 TRANSPOSED weights [N][K], packed: W1i | W2i | W1u | W2u
#define W1I_OFF 0
#define W2I_OFF (FEAT_DIM * HIDDEN_DIM)
#define W1U_OFF (W2I_OFF + HIDDEN_DIM * TOWER_DIM)
#define W2U_OFF (W1U_OFF + (GCN_DIM + TOWER_DIM) * HIDDEN_DIM)
#define W_TOTAL (W2U_OFF + HIDDEN_DIM * TOWER_DIM)
__device__ __half g_W16[W_TOTAL];

__device__ __forceinline__ void mma_f16(float* d, const unsigned* a, const unsigned* b) {
    asm volatile(
        "mma.sync.aligned.m16n8k16.row.col.f32.f16.f16.f32 "
        "{%0,%1,%2,%3}, {%4,%5,%6,%7}, {%8,%9}, {%0,%1,%2,%3};\n"
        : "+f"(d[0]), "+f"(d[1]), "+f"(d[2]), "+f"(d[3])
        : "r"(a[0]), "r"(a[1]), "r"(a[2]), "r"(a[3]), "r"(b[0]), "r"(b[1]));
}

__device__ __forceinline__ void cp16(uint32_t dst, const void* src, int szbytes) {
    asm volatile("cp.async.ca.shared.global [%0], [%1], 16, %2;"
                 :: "r"(dst), "l"(src), "r"(szbytes));
}

// ---------------- FP16 tensor-core GEMM, cp.async double-buffered ----------
// A [M,K] row-major fp16.  Bt [N,K] row-major fp16 (transposed weights).
// BM=BN=128, BK=32, 256 threads (8 warps, 64x32 warp tile, 4x4 m16n8k16).
// WHALF: store C as fp16 (RNE), else fp32.  L2NORM requires N==128 (grid.x==1).
template<bool RELU, bool L2NORM, bool WHALF>
__global__ __launch_bounds__(256)
void mma_gemm(const __half* __restrict__ A, int M, int N, int K,
              const __half* __restrict__ Bt, const float* __restrict__ bias,
              void* __restrict__ Cv)
{
    constexpr int BM = 128, BN = 128, BK = 32;
    constexpr int LDA = BK + 8;          // 40 halfs = 80 B/row; (20*row+t4)%32 all-bank
    constexpr int LDB = BK + 8;          // same for Bt rows (N rows of K halfs)
    constexpr int A_BUF = BM * LDA;      // halfs
    constexpr int B_BUF = BN * LDB;
    __shared__ __align__(16) __half smem[2 * A_BUF + 2 * B_BUF];   // 40,960 B

    __half* As = smem;
    __half* Bs = smem + 2 * A_BUF;
    float (*red)[17] = reinterpret_cast<float(*)[17]>(smem);  // epilogue alias
    float* scl = reinterpret_cast<float*>(smem) + BM * 17;

    const int tid  = threadIdx.x;
    const int warp = tid >> 5, lane = tid & 31;
    const int wy = warp >> 2, wx = warp & 3;     // warp tile rows wy*64, cols wx*32
    const int g  = lane >> 2, t4 = lane & 3;
    const int bm = blockIdx.y, bn = blockIdx.x;

    const uint32_t a_base = (uint32_t)__cvta_generic_to_shared(As);
    const uint32_t b_base = (uint32_t)__cvta_generic_to_shared(Bs);

    float acc[4][4][4];
    #pragma unroll
    for (int i = 0; i < 4; i++)
        #pragma unroll
        for (int j = 0; j < 4; j++)
            #pragma unroll
            for (int r = 0; r < 4; r++) acc[i][j][r] = 0.f;

    // 128 rows x 64 B per operand = 512 x 16B chunks each; 4 cp16 per thread
    auto issue = [&](int k0, int buf) {
        #pragma unroll
        for (int c = 0; c < 2; c++) {
            const int id = tid + c * 256;        // 0..511
            const int m  = id >> 2;              // row 0..127
            const int f  = (id & 3) * 8;         // k-offset in halfs (16B chunks)
            const int grow = bm * BM + m;
            const __half* src = A;
            int sz = 0;
            if (grow < M) { src = A + (size_t)grow * K + k0 + f; sz = 16; }
            cp16(a_base + (uint32_t)(buf * A_BUF + m * LDA + f) * 2, src, sz);
        }
        #pragma unroll
        for (int c = 0; c < 2; c++) {
            const int id = tid + c * 256;
            const int n  = id >> 2;
            const int f  = (id & 3) * 8;
            const __half* src = Bt + (size_t)(bn * BN + n) * K + k0 + f;
            cp16(b_base + (uint32_t)(buf * B_BUF + n * LDB + f) * 2, src, 16);
        }
        asm volatile("cp.async.commit_group;");
    };

    const int NT = K / BK;
    issue(0, 0);

    for (int it = 0; it < NT; it++) {
        const int buf = it & 1;
        if (it + 1 < NT) {
            issue((it + 1) * BK, buf ^ 1);
            asm volatile("cp.async.wait_group 1;");
        } else {
            asm volatile("cp.async.wait_group 0;");
        }
        __syncthreads();

        const unsigned* Aw = reinterpret_cast<const unsigned*>(As + buf * A_BUF);
        const unsigned* Bw = reinterpret_cast<const unsigned*>(Bs + buf * B_BUF);
        constexpr int WA = LDA / 2;   // 20 words per row
        constexpr int WB = LDB / 2;

        #pragma unroll
        for (int ks = 0; ks < 2; ks++) {          // two K=16 steps per tile
            const int kw = ks * 8;                // word offset of k-group
            unsigned a[4][4], b[4][2];
            #pragma unroll
            for (int mi = 0; mi < 4; mi++) {
                const int rb = wy * 64 + mi * 16;
                a[mi][0] = Aw[(rb + g)     * WA + kw + t4];
                a[mi][1] = Aw[(rb + 8 + g) * WA + kw + t4];
                a[mi][2] = Aw[(rb + g)     * WA + kw + 4 + t4];
                a[mi][3] = Aw[(rb + 8 + g) * WA + kw + 4 + t4];
            }
            #pragma unroll
            for (int ni = 0; ni < 4; ni++) {
                const int nb = wx * 32 + ni * 8;
                b[ni][0] = Bw[(nb + g) * WB + kw + t4];
                b[ni][1] = Bw[(nb + g) * WB + kw + 4 + t4];
            }
            #pragma unroll
            for (int mi = 0; mi < 4; mi++)
                #pragma unroll
                for (int ni = 0; ni < 4; ni++)
                    mma_f16(acc[mi][ni], a[mi], b[ni]);
        }
        __syncthreads();
    }

    // ---- epilogue: bias (+ReLU) ----
    #pragma unroll
    for (int ni = 0; ni < 4; ni++) {
        const int colw = wx * 32 + ni * 8 + t4 * 2;
        const float b0 = bias[bn * BN + colw];
        const float b1 = bias[bn * BN + colw + 1];
        #pragma unroll
        for (int mi = 0; mi < 4; mi++) {
            float v0 = acc[mi][ni][0] + b0;
            float v1 = acc[mi][ni][1] + b1;
            float v2 = acc[mi][ni][2] + b0;
            float v3 = acc[mi][ni][3] + b1;
            if (RELU) {
                v0 = fmaxf(v0, 0.f); v1 = fmaxf(v1, 0.f);
                v2 = fmaxf(v2, 0.f); v3 = fmaxf(v3, 0.f);
            }
            acc[mi][ni][0] = v0; acc[mi][ni][1] = v1;
            acc[mi][ni][2] = v2; acc[mi][ni][3] = v3;
        }
    }

    if (L2NORM) {
        const int slot = wx * 4 + t4;
        #pragma unroll
        for (int mi = 0; mi < 4; mi++) {
            const int rb = wy * 64 + mi * 16;
            float s0 = 0.f, s1 = 0.f;
            #pragma unroll
            for (int ni = 0; ni < 4; ni++) {
                s0 = fmaf(acc[mi][ni][0], acc[mi][ni][0], s0);
                s0 = fmaf(acc[mi][ni][1], acc[mi][ni][1], s0);
                s1 = fmaf(acc[mi][ni][2], acc[mi][ni][2], s1);
                s1 = fmaf(acc[mi][ni][3], acc[mi][ni][3], s1);
            }
            red[rb + g][slot]     = s0;
            red[rb + 8 + g][slot] = s1;
        }
        __syncthreads();
        if (tid < BM) {
            float s = 0.f;
            #pragma unroll
            for (int t = 0; t < 16; t++) s += red[tid][t];
            scl[tid] = 1.f / fmaxf(sqrtf(s), 1e-12f);
        }
        __syncthreads();
        #pragma unroll
        for (int mi = 0; mi < 4; mi++) {
            const int rb = wy * 64 + mi * 16;
            const float s0 = scl[rb + g];
            const float s1 = scl[rb + 8 + g];
            #pragma unroll
            for (int ni = 0; ni < 4; ni++) {
                acc[mi][ni][0] *= s0; acc[mi][ni][1] *= s0;
                acc[mi][ni][2] *= s1; acc[mi][ni][3] *= s1;
            }
        }
    }

    // ---- store ----
    #pragma unroll
    for (int mi = 0; mi < 4; mi++) {
        const int row0 = bm * BM + wy * 64 + mi * 16 + g;
        const int row1 = row0 + 8;
        #pragma unroll
        for (int ni = 0; ni < 4; ni++) {
            const int col = bn * BN + wx * 32 + ni * 8 + t4 * 2;
            if (WHALF) {
                __half* C = (__half*)Cv;
                if (row0 < M)
                    *reinterpret_cast<__half2*>(C + (size_t)row0 * N + col) =
                        __floats2half2_rn(acc[mi][ni][0], acc[mi][ni][1]);
                if (row1 < M)
                    *reinterpret_cast<__half2*>(C + (size_t)row1 * N + col) =
                        __floats2half2_rn(acc[mi][ni][2], acc[mi][ni][3]);
            } else {
                float* C = (float*)Cv;
                if (row0 < M)
                    *reinterpret_cast<float2*>(C + (size_t)row0 * N + col) =
                        make_float2(acc[mi][ni][0], acc[mi][ni][1]);
                if (row1 < M)
                    *reinterpret_cast<float2*>(C + (size_t)row1 * N + col) =
                        make_float2(acc[mi][ni][2], acc[mi][ni][3]);
            }
        }
    }
}

// --------- one-shot: fused item features -> fp16 [N_ITEMS][384] ------------
__global__ __launch_bounds__(256)
void convert_items(const float4* __restrict__ text, const float4* __restrict__ gcn,
                   __half* __restrict__ out)
{
    const int i = blockIdx.x * blockDim.x + threadIdx.x;   // over N_ITEMS*96 float4s
    if (i >= N_ITEMS * (FEAT_DIM / 4)) return;
    const int r = i / (FEAT_DIM / 4), c = i % (FEAT_DIM / 4);
    float4 v = (c < TEXT_DIM / 4) ? text[(size_t)r * (TEXT_DIM / 4) + c]
                                  : gcn[(size_t)r * (GCN_DIM / 4) + (c - TEXT_DIM / 4)];
    __half2 h0 = __floats2half2_rn(v.x, v.y);
    __half2 h1 = __floats2half2_rn(v.z, v.w);
    *reinterpret_cast<__half2*>(out + (size_t)i * 4)     = h0;
    *reinterpret_cast<__half2*>(out + (size_t)i * 4 + 2) = h1;
}

// --------- one-shot: weights transpose [K,N]->[N,K] + fp16 -----------------
__global__ __launch_bounds__(256)
void convert_weights(const float* __restrict__ w1i, const float* __restrict__ w2i,
                     const float* __restrict__ w1u, const float* __restrict__ w2u,
                     __half* __restrict__ dst)
{
    const int i = blockIdx.x * blockDim.x + threadIdx.x;
    if (i >= W_TOTAL) return;
    const float* w; int Kd, Nd, local;
    if      (i < W2I_OFF) { w = w1i; Kd = FEAT_DIM;            Nd = HIDDEN_DIM; local = i; }
    else if (i < W1U_OFF) { w = w2i; Kd = HIDDEN_DIM;          Nd = TOWER_DIM;  local = i - W2I_OFF; }
    else if (i < W2U_OFF) { w = w1u; Kd = GCN_DIM + TOWER_DIM; Nd = HIDDEN_DIM; local = i - W1U_OFF; }
    else                  { w = w2u; Kd = HIDDEN_DIM;          Nd = TOWER_DIM;  local = i - W2U_OFF; }
    const int n = local / Kd, k = local % Kd;
    dst[i] = __float2half_rn(w[(size_t)k * Nd + n]);
}

// ---------------- history gather + mean pool + fuse (fp16 out) -------------
__global__ __launch_bounds__(128)
void gather_kernel(const float* __restrict__ gcn_user,
                   const int* __restrict__ hist,
                   const float* __restrict__ item_emb,
                   __half* __restrict__ user_feat)
{
    const int u = blockIdx.x;
    const int t = threadIdx.x;  // 0..127 = embedding dim
    __shared__ int sidx[HIST];
    if (t < HIST) sidx[t] = hist[u * HIST + t];
    __syncthreads();

    float s = 0.f;
    #pragma unroll
    for (int j = 0; j < HIST; j++)
        s += item_emb[(long long)sidx[j] * TOWER_DIM + t];

    user_feat[(size_t)u * (GCN_DIM + TOWER_DIM) + t] =
        __float2half_rn(gcn_user[(size_t)u * GCN_DIM + t]);
    user_feat[(size_t)u * (GCN_DIM + TOWER_DIM) + GCN_DIM + t] =
        __float2half_rn(s * (1.0f / HIST));
}

// ---------------- launch -----------------------------------------------------
extern "C" void kernel_launch(void* const* d_in, const int* in_sizes, int n_in,
                              void* d_out, int out_size)
{
    const float* item_text = (const float*)d_in[0];
    const float* gcn_item  = (const float*)d_in[1];
    const float* gcn_user  = (const float*)d_in[2];
    const int*   hist      = (const int*)  d_in[3];
    const float* W1i = (const float*)d_in[4];
    const float* b1i = (const float*)d_in[5];
    const float* W2i = (const float*)d_in[6];
    const float* b2i = (const float*)d_in[7];
    const float* W1u = (const float*)d_in[8];
    const float* b1u = (const float*)d_in[9];
    const float* W2u = (const float*)d_in[10];
    const float* b2u = (const float*)d_in[11];
    float* out = (float*)d_out;

    __half *pAf, *pH, *pUF, *pHu, *pW;
    float *pItem;
    cudaGetSymbolAddress((void**)&pAf,   g_Af16);
    cudaGetSymbolAddress((void**)&pH,    g_H);
    cudaGetSymbolAddress((void**)&pItem, g_item_emb);
    cudaGetSymbolAddress((void**)&pUF,   g_user_feat);
    cudaGetSymbolAddress((void**)&pHu,   g_Hu);
    cudaGetSymbolAddress((void**)&pW,    g_W16);

    // one-shot conversions
    convert_items<<<CDIV(N_ITEMS * (FEAT_DIM / 4), 256), 256>>>(
        (const float4*)item_text, (const float4*)gcn_item, pAf);
    convert_weights<<<CDIV(W_TOTAL, 256), 256>>>(W1i, W2i, W1u, W2u, pW);

    const dim3 blk(256);

    // Item tower L1: H = relu(Af16 @ W1i + b1i) -> fp16
    mma_gemm<true, false, true><<<dim3(HIDDEN_DIM / 128, CDIV(N_ITEMS, 128)), blk>>>(
        pAf, N_ITEMS, HIDDEN_DIM, FEAT_DIM, pW + W1I_OFF, b1i, pH);

    // Item tower L2: item_emb = l2norm(H @ W2i + b2i) -> fp32
    mma_gemm<false, true, false><<<dim3(1, CDIV(N_ITEMS, 128)), blk>>>(
        pH, N_ITEMS, TOWER_DIM, HIDDEN_DIM, pW + W2I_OFF, b2i, pItem);

    // History gather + mean pool fused with gcn_user -> fp16
    gather_kernel<<<N_USERS, 128>>>(gcn_user, hist, pItem, pUF);

    // User tower L1: Hu = relu(user_feat @ W1u + b1u) -> fp16
    mma_gemm<true, false, true><<<dim3(HIDDEN_DIM / 128, CDIV(N_USERS, 128)), blk>>>(
        pUF, N_USERS, HIDDEN_DIM, GCN_DIM + TOWER_DIM, pW + W1U_OFF, b1u, pHu);

    // User tower L2: out = l2norm(Hu @ W2u + b2u) -> fp32
    mma_gemm<false, true, false><<<dim3(1, CDIV(N_USERS, 128)), blk>>>(
        pHu, N_USERS, TOWER_DIM, HIDDEN_DIM, pW + W2U_OFF, b2u, out);
}